// round 15
// baseline (speedup 1.0000x reference)
#include <cuda_runtime.h>
#include <cuda_fp16.h>
#include <math.h>
#include <stdint.h>

// Shapes (fixed)
#define D_HID 1024
#define SEQ   2048
#define BATCH 2
#define HEADS 16
#define HD    64
#define MROWS (BATCH*SEQ)                 // 4096
#define OUT_MAIN (MROWS*D_HID)            // 4194304
#define ATTN_ELEMS (MROWS*HEADS*HEADS)    // 1048576

// fp16 q/kv planes (GEMM outputs)
__device__ __half g_q16 [MROWS*D_HID];
__device__ __half g_kv16[MROWS*2*D_HID];  // packed rows: k | v
__device__ float  g_bkv[2*D_HID];         // bk || bv
__device__ float  g_cos[SEQ*(D_HID/2)];
__device__ float  g_sin[SEQ*(D_HID/2)];

// fp16 operand planes
__device__ __half g_in_h[MROWS*D_HID];
__device__ __half g_cx_h[MROWS*D_HID];
__device__ __half g_xs_h[MROWS*D_HID];
__device__ __half g_wt_h[4*D_HID*D_HID];  // W^T (Wq,Wk,Wv,Wo)

__device__ __forceinline__ uint32_t smem_u32(const void* p) {
    uint32_t a;
    asm("{ .reg .u64 t; cvta.to.shared.u64 t, %1; cvt.u32.u64 %0, t; }"
        : "=r"(a) : "l"(p));
    return a;
}

// ---------------------------------------------------------------------------
// Fused prep kernel (unchanged)
// ---------------------------------------------------------------------------
__global__ __launch_bounds__(256)
void prep_kernel(const float* __restrict__ inputs, const float* __restrict__ context,
                 const float* __restrict__ W0, const float* __restrict__ W1,
                 const float* __restrict__ W2, const float* __restrict__ W3,
                 const float* __restrict__ bk, const float* __restrict__ bv)
{
    int blk = blockIdx.x;
    int tid = threadIdx.x;

    if (blk < 8192) {
        int which = blk >> 12;
        int idx = ((blk & 4095) << 8) | tid;
        const float4* src = (const float4*)(which ? context : inputs);
        uint2* h = (uint2*)(which ? g_cx_h : g_in_h);
        float4 v = src[idx];
        __half2 p0 = __floats2half2_rn(v.x, v.y);
        __half2 p1 = __floats2half2_rn(v.z, v.w);
        uint2 u;
        u.x = *(uint32_t*)&p0;
        u.y = *(uint32_t*)&p1;
        h[idx] = u;
    } else if (blk < 12288) {
        __shared__ float t[32][33];
        int r  = blk - 8192;
        int z  = r >> 10;
        int bi = r & 1023;
        int x0 = (bi & 31) * 32;
        int y0 = (bi >> 5) * 32;
        const float* W = (z == 0) ? W0 : (z == 1) ? W1 : (z == 2) ? W2 : W3;
        __half* h = g_wt_h + (size_t)z * D_HID * D_HID;
        int tx = tid & 31, ty = tid >> 5;
        #pragma unroll
        for (int j = 0; j < 4; j++)
            t[ty + 8 * j][tx] = W[(size_t)(y0 + ty + 8 * j) * D_HID + x0 + tx];
        __syncthreads();
        #pragma unroll
        for (int j = 0; j < 4; j++) {
            int rr = ty + 8 * j;
            h[(size_t)(x0 + rr) * D_HID + y0 + tx] = __float2half_rn(t[tx][rr]);
        }
    } else if (blk < 16384) {
        int idx = ((blk - 12288) << 8) | tid;
        int s = idx >> 9;
        int j = idx & 511;
        float inv = expf(-(float)j * (9.210340371976184f / 512.0f));
        float arg = (float)s * inv;
        float sv, cv;
        sincosf(arg, &sv, &cv);
        g_cos[idx] = cv;
        g_sin[idx] = sv;
    } else {
        int i = ((blk - 16384) << 8) | tid;
        g_bkv[i] = (i < D_HID) ? bk[i] : bv[i - D_HID];
    }
}

// ---------------------------------------------------------------------------
// fp16 GEMM body — 6-stage cp.async pipeline (was 4)
//   CTA 256x128, 8 warps of 64x64, K-chunk 32.
// ---------------------------------------------------------------------------
#define KC 32
#define NSTAGE 6
#define PLANE_A 16384
#define PLANE_B 8192
#define STAGE_BYTES (PLANE_A + PLANE_B)      // 24576
#define GEMM_SMEM (NSTAGE*STAGE_BYTES)       // 147456
#define NCHUNK (D_HID/KC)

#define LDSM4(r0,r1,r2,r3,addr) \
    asm volatile("ldmatrix.sync.aligned.m8n8.x4.shared.b16 {%0,%1,%2,%3}, [%4];" \
        : "=r"(r0), "=r"(r1), "=r"(r2), "=r"(r3) : "r"(addr))

#define MMA_F16(d, a, b0v, b1v) \
    asm volatile("mma.sync.aligned.m16n8k16.row.col.f32.f16.f16.f32 " \
        "{%0,%1,%2,%3}, {%4,%5,%6,%7}, {%8,%9}, {%0,%1,%2,%3};" \
        : "+f"((d)[0]), "+f"((d)[1]), "+f"((d)[2]), "+f"((d)[3]) \
        : "r"((a)[0]), "r"((a)[1]), "r"((a)[2]), "r"((a)[3]), "r"(b0v), "r"(b1v))

template<int OUT_HALF>
__device__ __forceinline__
void gemm_body(const __half* __restrict__ Ah,
               const __half* __restrict__ Bh,
               const float* __restrict__ bias, void* __restrict__ Cv,
               int ldc, int nbaseB)
{
    extern __shared__ char smem[];
    uint32_t sb = smem_u32(smem);
    int tid = threadIdx.x, lane = tid & 31, wid = tid >> 5;
    int wm = (wid & 3) * 64;
    int wn = (wid >> 2) * 64;

    int mbaseA = blockIdx.y * 256;

    int lrow = tid >> 1;
    int lb0  = (tid & 1) * 2;

    uint32_t aOff[4]; int aSw[4];
    #pragma unroll
    for (int mt = 0; mt < 4; mt++) {
        int r = wm + mt * 16 + (lane & 7) + ((lane >> 3) & 1) * 8;
        aOff[mt] = r * 64;
        aSw[mt] = (r >> 1) & 3;
    }
    int g = lane >> 3;
    uint32_t bOff[4]; int bSw[4];
    #pragma unroll
    for (int pk = 0; pk < 4; pk++) {
        int r = wn + pk * 16 + ((g >> 1) << 3) + (lane & 7);
        bOff[pk] = r * 64;
        bSw[pk] = (r >> 1) & 3;
    }
    int aKb = lane >> 4;
    int bKb = g & 1;

    float acc[4][8][4];
    #pragma unroll
    for (int i = 0; i < 4; i++)
        #pragma unroll
        for (int j = 0; j < 8; j++)
            #pragma unroll
            for (int c = 0; c < 4; c++) acc[i][j][c] = 0.0f;

    #define LOAD_CHUNK(chunk, stage) do {                                        \
        uint32_t st0 = sb + (stage) * STAGE_BYTES;                               \
        int kk = (chunk) * KC;                                                   \
        _Pragma("unroll")                                                        \
        for (int rr = 0; rr < 2; rr++) {                                         \
            int r = lrow + rr * 128;                                             \
            int sw = (r >> 1) & 3;                                               \
            const __half* sh = Ah + (size_t)(mbaseA + r) * D_HID + kk;           \
            _Pragma("unroll")                                                    \
            for (int j = 0; j < 2; j++) {                                        \
                int blk = lb0 + j;                                               \
                uint32_t d = st0 + r * 64 + ((blk ^ sw) << 4);                   \
                asm volatile("cp.async.cg.shared.global [%0], [%1], 16;"         \
                             :: "r"(d), "l"(sh + blk * 8));                      \
            }                                                                    \
        }                                                                        \
        {                                                                        \
            int r = lrow;                                                        \
            int sw = (r >> 1) & 3;                                               \
            const __half* sh = Bh + (size_t)(nbaseB + r) * D_HID + kk;           \
            _Pragma("unroll")                                                    \
            for (int j = 0; j < 2; j++) {                                        \
                int blk = lb0 + j;                                               \
                uint32_t d = st0 + PLANE_A + r * 64 + ((blk ^ sw) << 4);         \
                asm volatile("cp.async.cg.shared.global [%0], [%1], 16;"         \
                             :: "r"(d), "l"(sh + blk * 8));                      \
            }                                                                    \
        }                                                                        \
    } while (0)

    #pragma unroll
    for (int s = 0; s < NSTAGE - 1; s++) {
        LOAD_CHUNK(s, s);
        asm volatile("cp.async.commit_group;");
    }

    int stage = 0;
    for (int i = 0; i < NCHUNK; i++) {
        asm volatile("cp.async.wait_group %0;" :: "n"(NSTAGE - 2));
        __syncthreads();

        if (i + NSTAGE - 1 < NCHUNK) {
            int ls = (stage + NSTAGE - 1) % NSTAGE;
            LOAD_CHUNK(i + NSTAGE - 1, ls);
        }
        asm volatile("cp.async.commit_group;");

        uint32_t st = sb + stage * STAGE_BYTES;
        stage = (stage + 1) % NSTAGE;
        #pragma unroll
        for (int s = 0; s < 2; s++) {
            uint32_t bh[16];
            #pragma unroll
            for (int pk = 0; pk < 4; pk++) {
                uint32_t ad = st + PLANE_A + bOff[pk]
                            + (((2 * s + bKb) ^ bSw[pk]) << 4);
                LDSM4(bh[pk*4+0], bh[pk*4+1], bh[pk*4+2], bh[pk*4+3], ad);
            }
            uint32_t ah[4][4];
            #pragma unroll
            for (int mt = 0; mt < 4; mt++) {
                uint32_t ad = st + aOff[mt] + (((2 * s + aKb) ^ aSw[mt]) << 4);
                LDSM4(ah[mt][0], ah[mt][1], ah[mt][2], ah[mt][3], ad);
            }
            #pragma unroll
            for (int mt = 0; mt < 4; mt++)
                #pragma unroll
                for (int nt = 0; nt < 8; nt++)
                    MMA_F16(acc[mt][nt], ah[mt], bh[nt*2], bh[nt*2+1]);
        }
    }

    #pragma unroll
    for (int mt = 0; mt < 4; mt++) {
        int row0 = blockIdx.y * 256 + wm + mt * 16 + (lane >> 2);
        #pragma unroll
        for (int nt = 0; nt < 8; nt++) {
            int col = nbaseB + wn + nt * 8 + (lane & 3) * 2;
            float b0 = bias[col], b1 = bias[col + 1];
            float o00 = acc[mt][nt][0] + b0, o01 = acc[mt][nt][1] + b1;
            float o10 = acc[mt][nt][2] + b0, o11 = acc[mt][nt][3] + b1;
            if (OUT_HALF) {
                __half* C = (__half*)Cv;
                __half2 p0 = __floats2half2_rn(o00, o01);
                __half2 p1 = __floats2half2_rn(o10, o11);
                *(__half2*)(C + (size_t)row0 * ldc + col) = p0;
                *(__half2*)(C + (size_t)(row0 + 8) * ldc + col) = p1;
            } else {
                float* C = (float*)Cv;
                float2 v0; v0.x = o00; v0.y = o01;
                float2 v1; v1.x = o10; v1.y = o11;
                *(float2*)(C + (size_t)row0 * ldc + col) = v0;
                *(float2*)(C + (size_t)(row0 + 8) * ldc + col) = v1;
            }
        }
    }
}

// Merged Q + KV projection: grid (24, 16). x<8 -> Q tile, x>=8 -> KV tile.
__global__ __launch_bounds__(256, 1)
void gemm_qkv(const float* __restrict__ bq)
{
    if (blockIdx.x < 8) {
        gemm_body<1>(g_in_h, g_wt_h, bq, g_q16, D_HID, blockIdx.x * 128);
    } else {
        gemm_body<1>(g_cx_h, g_wt_h + (size_t)D_HID * D_HID, g_bkv, g_kv16,
                     2 * D_HID, (blockIdx.x - 8) * 128);
    }
}

// Final O projection (fp32 out)
__global__ __launch_bounds__(256, 1)
void gemm_o(const float* __restrict__ bo, float* __restrict__ out)
{
    gemm_body<0>(g_xs_h, g_wt_h + (size_t)3 * D_HID * D_HID, bo, out,
                 D_HID, blockIdx.x * 128);
}

// ---------------------------------------------------------------------------
// Vectorized fused attention (exact R13 version): q fp32 smem (broadcast),
// k/v fp16 smem, 1 token per block.
// ---------------------------------------------------------------------------
#define SROWQ 68      // floats per q row
#define SROWH 72      // halves per k/v row

__global__ __launch_bounds__(256) void attn_fused_kernel(float* __restrict__ attn_out,
                                                         int write_attn)
{
    __shared__ float  sq[16 * SROWQ];
    __shared__ __half sk[16 * SROWH];
    __shared__ __half sv[16 * SROWH];
    __shared__ float  sc[16][17];

    int token = blockIdx.x;
    int tid   = threadIdx.x;
    int s     = token & (SEQ - 1);
    int b     = token >> 11;

    const uint2* qrow = (const uint2*)(g_q16  + (size_t)token * D_HID);
    const uint2* krow = (const uint2*)(g_kv16 + (size_t)token * (2 * D_HID));
    const uint2* vrow = krow + (D_HID / 4);

    {
        int i0 = tid * 4;
        int j0 = i0 & 511;
        const float4* cs = (const float4*)(g_cos + (s << 9) + j0);
        const float4* sn = (const float4*)(g_sin + (s << 9) + j0);
        float4 c4 = cs[0], s4 = sn[0];

        uint2 uq  = qrow[tid],       uk  = krow[tid];
        uint2 uqp = qrow[tid ^ 128], ukp = krow[tid ^ 128];
        uint2 uv  = vrow[tid];
        float2 q01 = __half22float2(*(__half2*)&uq.x);
        float2 q23 = __half22float2(*(__half2*)&uq.y);
        float2 qp01 = __half22float2(*(__half2*)&uqp.x);
        float2 qp23 = __half22float2(*(__half2*)&uqp.y);
        float2 k01 = __half22float2(*(__half2*)&uk.x);
        float2 k23 = __half22float2(*(__half2*)&uk.y);
        float2 kp01 = __half22float2(*(__half2*)&ukp.x);
        float2 kp23 = __half22float2(*(__half2*)&ukp.y);

        float sgn = (i0 < 512) ? -1.0f : 1.0f;
        float4 rq;
        float2 rk01, rk23;
        rq.x = q01.x * c4.x + sgn * qp01.x * s4.x;
        rq.y = q01.y * c4.y + sgn * qp01.y * s4.y;
        rq.z = q23.x * c4.z + sgn * qp23.x * s4.z;
        rq.w = q23.y * c4.w + sgn * qp23.y * s4.w;
        rk01.x = k01.x * c4.x + sgn * kp01.x * s4.x;
        rk01.y = k01.y * c4.y + sgn * kp01.y * s4.y;
        rk23.x = k23.x * c4.z + sgn * kp23.x * s4.z;
        rk23.y = k23.y * c4.w + sgn * kp23.y * s4.w;

        int row = tid >> 4;
        int c4i = tid & 15;
        *(float4*)(sq + row * SROWQ + c4i * 4) = rq;
        __half2 hk0 = __floats2half2_rn(rk01.x, rk01.y);
        __half2 hk1 = __floats2half2_rn(rk23.x, rk23.y);
        uint2 ukv;
        ukv.x = *(uint32_t*)&hk0;
        ukv.y = *(uint32_t*)&hk1;
        *(uint2*)(sk + row * SROWH + c4i * 4) = ukv;
        *(uint2*)(sv + row * SROWH + c4i * 4) = uv;   // v stored raw fp16
    }
    __syncthreads();

    int h = tid >> 4, t = tid & 15;
    {
        const float4* q4 = (const float4*)(sq + h * SROWQ);
        const uint4*  k8 = (const uint4*)(sk + t * SROWH);
        float ax = 0.0f, ay = 0.0f, az = 0.0f, aw = 0.0f;
        #pragma unroll
        for (int jj = 0; jj < 8; jj++) {
            float4 a0 = q4[2 * jj], a1 = q4[2 * jj + 1];
            uint4 kk = k8[jj];
            float2 b0 = __half22float2(*(__half2*)&kk.x);
            float2 b1 = __half22float2(*(__half2*)&kk.y);
            float2 b2 = __half22float2(*(__half2*)&kk.z);
            float2 b3 = __half22float2(*(__half2*)&kk.w);
            ax = fmaf(a0.x, b0.x, ax);
            ay = fmaf(a0.y, b0.y, ay);
            az = fmaf(a0.z, b1.x, az);
            aw = fmaf(a0.w, b1.y, aw);
            ax = fmaf(a1.x, b2.x, ax);
            ay = fmaf(a1.y, b2.y, ay);
            az = fmaf(a1.z, b3.x, az);
            aw = fmaf(a1.w, b3.y, aw);
        }
        float sco = (ax + ay + az + aw) * 0.125f;

        float m = sco;
        #pragma unroll
        for (int o = 8; o; o >>= 1)
            m = fmaxf(m, __shfl_xor_sync(0xffffffffu, m, o));
        float e = expf(sco - m);
        float sum = e;
        #pragma unroll
        for (int o = 8; o; o >>= 1)
            sum += __shfl_xor_sync(0xffffffffu, sum, o);
        float p = e / sum;
        sc[h][t] = p;
        if (write_attn)
            attn_out[(size_t)token * 256 + tid] = p;
    }
    __syncthreads();

    {
        int d4 = tid & 15;
        float4 acc = make_float4(0.0f, 0.0f, 0.0f, 0.0f);
        #pragma unroll
        for (int tt = 0; tt < 16; tt++) {
            float p = sc[h][tt];
            uint2 uv = *(const uint2*)(sv + tt * SROWH + d4 * 4);
            float2 v01 = __half22float2(*(__half2*)&uv.x);
            float2 v23 = __half22float2(*(__half2*)&uv.y);
            acc.x = fmaf(p, v01.x, acc.x);
            acc.y = fmaf(p, v01.y, acc.y);
            acc.z = fmaf(p, v23.x, acc.z);
            acc.w = fmaf(p, v23.y, acc.w);
        }
        size_t xbase = ((size_t)b * SEQ + (h * 128 + (s >> 4))) * D_HID
                     + ((s & 15) << 6) + d4 * 4;
        __half2 p0 = __floats2half2_rn(acc.x, acc.y);
        __half2 p1 = __floats2half2_rn(acc.z, acc.w);
        uint2 u;
        u.x = *(uint32_t*)&p0;
        u.y = *(uint32_t*)&p1;
        *(uint2*)(g_xs_h + xbase) = u;
    }
}

// ---------------------------------------------------------------------------
extern "C" void kernel_launch(void* const* d_in, const int* in_sizes, int n_in,
                              void* d_out, int out_size)
{
    const float* inputs  = (const float*)d_in[0];
    const float* context = (const float*)d_in[1];
    const float* Wq = (const float*)d_in[2];
    const float* bq = (const float*)d_in[3];
    const float* Wk = (const float*)d_in[4];
    const float* bk = (const float*)d_in[5];
    const float* Wv = (const float*)d_in[6];
    const float* bv = (const float*)d_in[7];
    const float* Wo = (const float*)d_in[8];
    const float* bo = (const float*)d_in[9];
    float* out = (float*)d_out;

    cudaFuncSetAttribute(gemm_qkv,
                         cudaFuncAttributeMaxDynamicSharedMemorySize, GEMM_SMEM);
    cudaFuncSetAttribute(gemm_o,
                         cudaFuncAttributeMaxDynamicSharedMemorySize, GEMM_SMEM);

    // 1) fused prep
    prep_kernel<<<16392, 256>>>(inputs, context, Wq, Wk, Wv, Wo, bk, bv);

    // 2) merged Q + K/V projections (one launch, 384 CTAs)
    {
        dim3 g(24, 16);
        gemm_qkv<<<g, 256, GEMM_SMEM>>>(bq);
    }

    // 3) fused RoPE + head-attention + scrambled fp16 ctx (1 token/block)
    int write_attn = (out_size >= OUT_MAIN + ATTN_ELEMS) ? 1 : 0;
    attn_fused_kernel<<<MROWS, 256>>>(out + OUT_MAIN, write_attn);

    // 4) final projection (fp32 out to d_out)
    {
        dim3 g(8, 16);
        gemm_o<<<g, 256, GEMM_SMEM>>>(bo, out);
    }
}

// round 16
// speedup vs baseline: 1.0456x; 1.0456x over previous
#include <cuda_runtime.h>
#include <cuda_fp16.h>
#include <math.h>
#include <stdint.h>

// Shapes (fixed)
#define D_HID 1024
#define SEQ   2048
#define BATCH 2
#define HEADS 16
#define HD    64
#define MROWS (BATCH*SEQ)                 // 4096
#define OUT_MAIN (MROWS*D_HID)            // 4194304
#define ATTN_ELEMS (MROWS*HEADS*HEADS)    // 1048576

// fp16 q/kv planes (GEMM outputs)
__device__ __half g_q16 [MROWS*D_HID];
__device__ __half g_kv16[MROWS*2*D_HID];  // packed rows: k | v
__device__ float  g_bkv[2*D_HID];         // bk || bv
__device__ float  g_cos[SEQ*(D_HID/2)];
__device__ float  g_sin[SEQ*(D_HID/2)];

// fp16 operand planes
__device__ __half g_in_h[MROWS*D_HID];
__device__ __half g_cx_h[MROWS*D_HID];
__device__ __half g_xs_h[MROWS*D_HID];
__device__ __half g_wt_h[4*D_HID*D_HID];  // W^T (Wq,Wk,Wv,Wo)

__device__ __forceinline__ uint32_t smem_u32(const void* p) {
    uint32_t a;
    asm("{ .reg .u64 t; cvta.to.shared.u64 t, %1; cvt.u32.u64 %0, t; }"
        : "=r"(a) : "l"(p));
    return a;
}

// ---------------------------------------------------------------------------
// Fused prep kernel
// ---------------------------------------------------------------------------
__global__ __launch_bounds__(256)
void prep_kernel(const float* __restrict__ inputs, const float* __restrict__ context,
                 const float* __restrict__ W0, const float* __restrict__ W1,
                 const float* __restrict__ W2, const float* __restrict__ W3,
                 const float* __restrict__ bk, const float* __restrict__ bv)
{
    int blk = blockIdx.x;
    int tid = threadIdx.x;

    if (blk < 8192) {
        int which = blk >> 12;
        int idx = ((blk & 4095) << 8) | tid;
        const float4* src = (const float4*)(which ? context : inputs);
        uint2* h = (uint2*)(which ? g_cx_h : g_in_h);
        float4 v = src[idx];
        __half2 p0 = __floats2half2_rn(v.x, v.y);
        __half2 p1 = __floats2half2_rn(v.z, v.w);
        uint2 u;
        u.x = *(uint32_t*)&p0;
        u.y = *(uint32_t*)&p1;
        h[idx] = u;
    } else if (blk < 12288) {
        __shared__ float t[32][33];
        int r  = blk - 8192;
        int z  = r >> 10;
        int bi = r & 1023;
        int x0 = (bi & 31) * 32;
        int y0 = (bi >> 5) * 32;
        const float* W = (z == 0) ? W0 : (z == 1) ? W1 : (z == 2) ? W2 : W3;
        __half* h = g_wt_h + (size_t)z * D_HID * D_HID;
        int tx = tid & 31, ty = tid >> 5;
        #pragma unroll
        for (int j = 0; j < 4; j++)
            t[ty + 8 * j][tx] = W[(size_t)(y0 + ty + 8 * j) * D_HID + x0 + tx];
        __syncthreads();
        #pragma unroll
        for (int j = 0; j < 4; j++) {
            int rr = ty + 8 * j;
            h[(size_t)(x0 + rr) * D_HID + y0 + tx] = __float2half_rn(t[tx][rr]);
        }
    } else if (blk < 16384) {
        int idx = ((blk - 12288) << 8) | tid;
        int s = idx >> 9;
        int j = idx & 511;
        float inv = expf(-(float)j * (9.210340371976184f / 512.0f));
        float arg = (float)s * inv;
        float sv, cv;
        sincosf(arg, &sv, &cv);
        g_cos[idx] = cv;
        g_sin[idx] = sv;
    } else {
        int i = ((blk - 16384) << 8) | tid;
        g_bkv[i] = (i < D_HID) ? bk[i] : bv[i - D_HID];
    }
}

// ---------------------------------------------------------------------------
// fp16 GEMM body — 4-stage cp.async pipeline (R13 champion config)
//   CTA 256x128, 8 warps of 64x64, K-chunk 32.
// ---------------------------------------------------------------------------
#define KC 32
#define NSTAGE 4
#define PLANE_A 16384
#define PLANE_B 8192
#define STAGE_BYTES (PLANE_A + PLANE_B)      // 24576
#define GEMM_SMEM (NSTAGE*STAGE_BYTES)       // 98304
#define NCHUNK (D_HID/KC)

#define LDSM4(r0,r1,r2,r3,addr) \
    asm volatile("ldmatrix.sync.aligned.m8n8.x4.shared.b16 {%0,%1,%2,%3}, [%4];" \
        : "=r"(r0), "=r"(r1), "=r"(r2), "=r"(r3) : "r"(addr))

#define MMA_F16(d, a, b0v, b1v) \
    asm volatile("mma.sync.aligned.m16n8k16.row.col.f32.f16.f16.f32 " \
        "{%0,%1,%2,%3}, {%4,%5,%6,%7}, {%8,%9}, {%0,%1,%2,%3};" \
        : "+f"((d)[0]), "+f"((d)[1]), "+f"((d)[2]), "+f"((d)[3]) \
        : "r"((a)[0]), "r"((a)[1]), "r"((a)[2]), "r"((a)[3]), "r"(b0v), "r"(b1v))

template<int OUT_HALF>
__device__ __forceinline__
void gemm_body(const __half* __restrict__ Ah,
               const __half* __restrict__ Bh,
               const float* __restrict__ bias, void* __restrict__ Cv,
               int ldc, int nbaseB)
{
    extern __shared__ char smem[];
    uint32_t sb = smem_u32(smem);
    int tid = threadIdx.x, lane = tid & 31, wid = tid >> 5;
    int wm = (wid & 3) * 64;
    int wn = (wid >> 2) * 64;

    int mbaseA = blockIdx.y * 256;

    int lrow = tid >> 1;
    int lb0  = (tid & 1) * 2;

    uint32_t aOff[4]; int aSw[4];
    #pragma unroll
    for (int mt = 0; mt < 4; mt++) {
        int r = wm + mt * 16 + (lane & 7) + ((lane >> 3) & 1) * 8;
        aOff[mt] = r * 64;
        aSw[mt] = (r >> 1) & 3;
    }
    int g = lane >> 3;
    uint32_t bOff[4]; int bSw[4];
    #pragma unroll
    for (int pk = 0; pk < 4; pk++) {
        int r = wn + pk * 16 + ((g >> 1) << 3) + (lane & 7);
        bOff[pk] = r * 64;
        bSw[pk] = (r >> 1) & 3;
    }
    int aKb = lane >> 4;
    int bKb = g & 1;

    float acc[4][8][4];
    #pragma unroll
    for (int i = 0; i < 4; i++)
        #pragma unroll
        for (int j = 0; j < 8; j++)
            #pragma unroll
            for (int c = 0; c < 4; c++) acc[i][j][c] = 0.0f;

    #define LOAD_CHUNK(chunk, stage) do {                                        \
        uint32_t st0 = sb + (stage) * STAGE_BYTES;                               \
        int kk = (chunk) * KC;                                                   \
        _Pragma("unroll")                                                        \
        for (int rr = 0; rr < 2; rr++) {                                         \
            int r = lrow + rr * 128;                                             \
            int sw = (r >> 1) & 3;                                               \
            const __half* sh = Ah + (size_t)(mbaseA + r) * D_HID + kk;           \
            _Pragma("unroll")                                                    \
            for (int j = 0; j < 2; j++) {                                        \
                int blk = lb0 + j;                                               \
                uint32_t d = st0 + r * 64 + ((blk ^ sw) << 4);                   \
                asm volatile("cp.async.cg.shared.global [%0], [%1], 16;"         \
                             :: "r"(d), "l"(sh + blk * 8));                      \
            }                                                                    \
        }                                                                        \
        {                                                                        \
            int r = lrow;                                                        \
            int sw = (r >> 1) & 3;                                               \
            const __half* sh = Bh + (size_t)(nbaseB + r) * D_HID + kk;           \
            _Pragma("unroll")                                                    \
            for (int j = 0; j < 2; j++) {                                        \
                int blk = lb0 + j;                                               \
                uint32_t d = st0 + PLANE_A + r * 64 + ((blk ^ sw) << 4);         \
                asm volatile("cp.async.cg.shared.global [%0], [%1], 16;"         \
                             :: "r"(d), "l"(sh + blk * 8));                      \
            }                                                                    \
        }                                                                        \
    } while (0)

    #pragma unroll
    for (int s = 0; s < NSTAGE - 1; s++) {
        LOAD_CHUNK(s, s);
        asm volatile("cp.async.commit_group;");
    }

    for (int i = 0; i < NCHUNK; i++) {
        asm volatile("cp.async.wait_group %0;" :: "n"(NSTAGE - 2));
        __syncthreads();

        if (i + NSTAGE - 1 < NCHUNK)
            LOAD_CHUNK(i + NSTAGE - 1, (i + NSTAGE - 1) & (NSTAGE - 1));
        asm volatile("cp.async.commit_group;");

        uint32_t st = sb + (i & (NSTAGE - 1)) * STAGE_BYTES;
        #pragma unroll
        for (int s = 0; s < 2; s++) {
            uint32_t bh[16];
            #pragma unroll
            for (int pk = 0; pk < 4; pk++) {
                uint32_t ad = st + PLANE_A + bOff[pk]
                            + (((2 * s + bKb) ^ bSw[pk]) << 4);
                LDSM4(bh[pk*4+0], bh[pk*4+1], bh[pk*4+2], bh[pk*4+3], ad);
            }
            uint32_t ah[4][4];
            #pragma unroll
            for (int mt = 0; mt < 4; mt++) {
                uint32_t ad = st + aOff[mt] + (((2 * s + aKb) ^ aSw[mt]) << 4);
                LDSM4(ah[mt][0], ah[mt][1], ah[mt][2], ah[mt][3], ad);
            }
            #pragma unroll
            for (int mt = 0; mt < 4; mt++)
                #pragma unroll
                for (int nt = 0; nt < 8; nt++)
                    MMA_F16(acc[mt][nt], ah[mt], bh[nt*2], bh[nt*2+1]);
        }
    }

    #pragma unroll
    for (int mt = 0; mt < 4; mt++) {
        int row0 = blockIdx.y * 256 + wm + mt * 16 + (lane >> 2);
        #pragma unroll
        for (int nt = 0; nt < 8; nt++) {
            int col = nbaseB + wn + nt * 8 + (lane & 3) * 2;
            float b0 = bias[col], b1 = bias[col + 1];
            float o00 = acc[mt][nt][0] + b0, o01 = acc[mt][nt][1] + b1;
            float o10 = acc[mt][nt][2] + b0, o11 = acc[mt][nt][3] + b1;
            if (OUT_HALF) {
                __half* C = (__half*)Cv;
                __half2 p0 = __floats2half2_rn(o00, o01);
                __half2 p1 = __floats2half2_rn(o10, o11);
                *(__half2*)(C + (size_t)row0 * ldc + col) = p0;
                *(__half2*)(C + (size_t)(row0 + 8) * ldc + col) = p1;
            } else {
                float* C = (float*)Cv;
                float2 v0; v0.x = o00; v0.y = o01;
                float2 v1; v1.x = o10; v1.y = o11;
                *(float2*)(C + (size_t)row0 * ldc + col) = v0;
                *(float2*)(C + (size_t)(row0 + 8) * ldc + col) = v1;
            }
        }
    }
}

// Merged Q + KV projection: grid (24, 16). x<8 -> Q tile, x>=8 -> KV tile.
__global__ __launch_bounds__(256, 1)
void gemm_qkv(const float* __restrict__ bq)
{
    if (blockIdx.x < 8) {
        gemm_body<1>(g_in_h, g_wt_h, bq, g_q16, D_HID, blockIdx.x * 128);
    } else {
        gemm_body<1>(g_cx_h, g_wt_h + (size_t)D_HID * D_HID, g_bkv, g_kv16,
                     2 * D_HID, (blockIdx.x - 8) * 128);
    }
}

// Final O projection (fp32 out)
__global__ __launch_bounds__(256, 1)
void gemm_o(const float* __restrict__ bo, float* __restrict__ out)
{
    gemm_body<0>(g_xs_h, g_wt_h + (size_t)3 * D_HID * D_HID, bo, out,
                 D_HID, blockIdx.x * 128);
}

// ---------------------------------------------------------------------------
// Vectorized fused attention (R13 champion): q fp32 smem (broadcast reads),
// k/v fp16 smem, 1 token per block.
// ---------------------------------------------------------------------------
#define SROWQ 68      // floats per q row
#define SROWH 72      // halves per k/v row

__global__ __launch_bounds__(256) void attn_fused_kernel(float* __restrict__ attn_out,
                                                         int write_attn)
{
    __shared__ float  sq[16 * SROWQ];
    __shared__ __half sk[16 * SROWH];
    __shared__ __half sv[16 * SROWH];
    __shared__ float  sc[16][17];

    int token = blockIdx.x;
    int tid   = threadIdx.x;
    int s     = token & (SEQ - 1);
    int b     = token >> 11;

    const uint2* qrow = (const uint2*)(g_q16  + (size_t)token * D_HID);
    const uint2* krow = (const uint2*)(g_kv16 + (size_t)token * (2 * D_HID));
    const uint2* vrow = krow + (D_HID / 4);

    {
        int i0 = tid * 4;
        int j0 = i0 & 511;
        const float4* cs = (const float4*)(g_cos + (s << 9) + j0);
        const float4* sn = (const float4*)(g_sin + (s << 9) + j0);
        float4 c4 = cs[0], s4 = sn[0];

        uint2 uq  = qrow[tid],       uk  = krow[tid];
        uint2 uqp = qrow[tid ^ 128], ukp = krow[tid ^ 128];
        uint2 uv  = vrow[tid];
        float2 q01 = __half22float2(*(__half2*)&uq.x);
        float2 q23 = __half22float2(*(__half2*)&uq.y);
        float2 qp01 = __half22float2(*(__half2*)&uqp.x);
        float2 qp23 = __half22float2(*(__half2*)&uqp.y);
        float2 k01 = __half22float2(*(__half2*)&uk.x);
        float2 k23 = __half22float2(*(__half2*)&uk.y);
        float2 kp01 = __half22float2(*(__half2*)&ukp.x);
        float2 kp23 = __half22float2(*(__half2*)&ukp.y);

        float sgn = (i0 < 512) ? -1.0f : 1.0f;
        float4 rq;
        float2 rk01, rk23;
        rq.x = q01.x * c4.x + sgn * qp01.x * s4.x;
        rq.y = q01.y * c4.y + sgn * qp01.y * s4.y;
        rq.z = q23.x * c4.z + sgn * qp23.x * s4.z;
        rq.w = q23.y * c4.w + sgn * qp23.y * s4.w;
        rk01.x = k01.x * c4.x + sgn * kp01.x * s4.x;
        rk01.y = k01.y * c4.y + sgn * kp01.y * s4.y;
        rk23.x = k23.x * c4.z + sgn * kp23.x * s4.z;
        rk23.y = k23.y * c4.w + sgn * kp23.y * s4.w;

        int row = tid >> 4;
        int c4i = tid & 15;
        *(float4*)(sq + row * SROWQ + c4i * 4) = rq;
        __half2 hk0 = __floats2half2_rn(rk01.x, rk01.y);
        __half2 hk1 = __floats2half2_rn(rk23.x, rk23.y);
        uint2 ukv;
        ukv.x = *(uint32_t*)&hk0;
        ukv.y = *(uint32_t*)&hk1;
        *(uint2*)(sk + row * SROWH + c4i * 4) = ukv;
        *(uint2*)(sv + row * SROWH + c4i * 4) = uv;   // v stored raw fp16
    }
    __syncthreads();

    int h = tid >> 4, t = tid & 15;
    {
        const float4* q4 = (const float4*)(sq + h * SROWQ);
        const uint4*  k8 = (const uint4*)(sk + t * SROWH);
        float ax = 0.0f, ay = 0.0f, az = 0.0f, aw = 0.0f;
        #pragma unroll
        for (int jj = 0; jj < 8; jj++) {
            float4 a0 = q4[2 * jj], a1 = q4[2 * jj + 1];
            uint4 kk = k8[jj];
            float2 b0 = __half22float2(*(__half2*)&kk.x);
            float2 b1 = __half22float2(*(__half2*)&kk.y);
            float2 b2 = __half22float2(*(__half2*)&kk.z);
            float2 b3 = __half22float2(*(__half2*)&kk.w);
            ax = fmaf(a0.x, b0.x, ax);
            ay = fmaf(a0.y, b0.y, ay);
            az = fmaf(a0.z, b1.x, az);
            aw = fmaf(a0.w, b1.y, aw);
            ax = fmaf(a1.x, b2.x, ax);
            ay = fmaf(a1.y, b2.y, ay);
            az = fmaf(a1.z, b3.x, az);
            aw = fmaf(a1.w, b3.y, aw);
        }
        float sco = (ax + ay + az + aw) * 0.125f;

        float m = sco;
        #pragma unroll
        for (int o = 8; o; o >>= 1)
            m = fmaxf(m, __shfl_xor_sync(0xffffffffu, m, o));
        float e = expf(sco - m);
        float sum = e;
        #pragma unroll
        for (int o = 8; o; o >>= 1)
            sum += __shfl_xor_sync(0xffffffffu, sum, o);
        float p = e / sum;
        sc[h][t] = p;
        if (write_attn)
            attn_out[(size_t)token * 256 + tid] = p;
    }
    __syncthreads();

    {
        int d4 = tid & 15;
        float4 acc = make_float4(0.0f, 0.0f, 0.0f, 0.0f);
        #pragma unroll
        for (int tt = 0; tt < 16; tt++) {
            float p = sc[h][tt];
            uint2 uv = *(const uint2*)(sv + tt * SROWH + d4 * 4);
            float2 v01 = __half22float2(*(__half2*)&uv.x);
            float2 v23 = __half22float2(*(__half2*)&uv.y);
            acc.x = fmaf(p, v01.x, acc.x);
            acc.y = fmaf(p, v01.y, acc.y);
            acc.z = fmaf(p, v23.x, acc.z);
            acc.w = fmaf(p, v23.y, acc.w);
        }
        size_t xbase = ((size_t)b * SEQ + (h * 128 + (s >> 4))) * D_HID
                     + ((s & 15) << 6) + d4 * 4;
        __half2 p0 = __floats2half2_rn(acc.x, acc.y);
        __half2 p1 = __floats2half2_rn(acc.z, acc.w);
        uint2 u;
        u.x = *(uint32_t*)&p0;
        u.y = *(uint32_t*)&p1;
        *(uint2*)(g_xs_h + xbase) = u;
    }
}

// ---------------------------------------------------------------------------
extern "C" void kernel_launch(void* const* d_in, const int* in_sizes, int n_in,
                              void* d_out, int out_size)
{
    const float* inputs  = (const float*)d_in[0];
    const float* context = (const float*)d_in[1];
    const float* Wq = (const float*)d_in[2];
    const float* bq = (const float*)d_in[3];
    const float* Wk = (const float*)d_in[4];
    const float* bk = (const float*)d_in[5];
    const float* Wv = (const float*)d_in[6];
    const float* bv = (const float*)d_in[7];
    const float* Wo = (const float*)d_in[8];
    const float* bo = (const float*)d_in[9];
    float* out = (float*)d_out;

    cudaFuncSetAttribute(gemm_qkv,
                         cudaFuncAttributeMaxDynamicSharedMemorySize, GEMM_SMEM);
    cudaFuncSetAttribute(gemm_o,
                         cudaFuncAttributeMaxDynamicSharedMemorySize, GEMM_SMEM);

    // 1) fused prep
    prep_kernel<<<16392, 256>>>(inputs, context, Wq, Wk, Wv, Wo, bk, bv);

    // 2) merged Q + K/V projections (one launch, 384 CTAs)
    {
        dim3 g(24, 16);
        gemm_qkv<<<g, 256, GEMM_SMEM>>>(bq);
    }

    // 3) fused RoPE + head-attention + scrambled fp16 ctx (1 token/block)
    int write_attn = (out_size >= OUT_MAIN + ATTN_ELEMS) ? 1 : 0;
    attn_fused_kernel<<<MROWS, 256>>>(out + OUT_MAIN, write_attn);

    // 4) final projection (fp32 out to d_out)
    {
        dim3 g(8, 16);
        gemm_o<<<g, 256, GEMM_SMEM>>>(bo, out);
    }
}